// round 16
// baseline (speedup 1.0000x reference)
#include <cuda_runtime.h>
#include <cstdint>

#define Bsz 256
#define Tsz 128
#define Fsz 256
#define Hsz 512
#define Csz 10

// Scratch: proj/h buffers, written in place by the recurrence.
__device__ float g_buf0[Bsz * Tsz * Hsz];   // 64 MB
__device__ float g_buf1[Bsz * Tsz * Hsz];   // 64 MB

// Distributed barrier: one padded flag per CTA (128B apart).
#define REC_NBLK 128
__device__ unsigned g_flag[REC_NBLK * 32];

__global__ void reset_flags()
{
    if (threadIdx.x < REC_NBLK) g_flag[threadIdx.x * 32] = 0u;
}

// ---------------------------------------------------------------------------
// TF32 helpers (shared by recurrence and projection).
// ---------------------------------------------------------------------------
__device__ __forceinline__ uint32_t f2tf32(float x)
{
    uint32_t r;
    asm("cvt.rna.tf32.f32 %0, %1;" : "=r"(r) : "f"(x));
    return r;
}

__device__ __forceinline__ void mma_tf32(
    float& d0, float& d1, float& d2, float& d3,
    uint32_t a0, uint32_t a1, uint32_t a2, uint32_t a3,
    uint32_t b0, uint32_t b1)
{
    asm volatile(
        "mma.sync.aligned.m16n8k8.row.col.f32.tf32.tf32.f32 "
        "{%0,%1,%2,%3}, {%4,%5,%6,%7}, {%8,%9}, {%0,%1,%2,%3};\n"
        : "+f"(d0), "+f"(d1), "+f"(d2), "+f"(d3)
        : "r"(a0), "r"(a1), "r"(a2), "r"(a3), "r"(b0), "r"(b1));
}

// Split one fp32 value into tf32 hi + lo residual (as tf32-able f32).
__device__ __forceinline__ void split_tf32(float v, uint32_t& hi, uint32_t& lo)
{
    hi = f2tf32(v);
    lo = __float_as_uint(v - __uint_as_float(hi));
}

// ---------------------------------------------------------------------------
// Tensor-core projection GEMM (unchanged from R14/R15 — passing).
// out[m,n] = sum_k A[m,k]*Wt[n,k] + b1[n]+b2[n]. 3xTF32 split.
// ---------------------------------------------------------------------------
#define PAP 36
#define PJS_B (128 * PAP)
#define PJ_SMEM_FLOATS (128 * PAP + 64 * PAP)
#define PJ_SMEM_BYTES (PJ_SMEM_FLOATS * 4)   // 27648 B

__global__ void __launch_bounds__(256, 2) proj_mma(
    const float* __restrict__ A, const float* __restrict__ Wt,
    const float* __restrict__ bias1, const float* __restrict__ bias2,
    float* __restrict__ out, int K)
{
    extern __shared__ float psm[];
    float* As = psm;
    float* Bs = psm + PJS_B;

    const int tid  = threadIdx.x;
    const int w    = tid >> 5;
    const int lane = tid & 31;
    const int wm   = w & 3;
    const int wn   = w >> 2;
    const int g    = lane >> 2;
    const int tg   = lane & 3;

    const int m0 = blockIdx.y * 128;
    const int n0 = blockIdx.x * 64;

    const int arow  = tid >> 1;
    const int apart = (tid & 1) * 16;
    const float* apg = A + (size_t)(m0 + arow) * K + apart;
    const int brow  = tid >> 2;
    const int bpart = (tid & 3) * 8;
    const float* bpg = Wt + (size_t)(n0 + brow) * K + bpart;

    float4 ra[4], rb[2];
#pragma unroll
    for (int u = 0; u < 4; ++u)
        ra[u] = *reinterpret_cast<const float4*>(apg + u * 4);
#pragma unroll
    for (int u = 0; u < 2; ++u)
        rb[u] = *reinterpret_cast<const float4*>(bpg + u * 4);

    float acc[2][4][4];
#pragma unroll
    for (int mf = 0; mf < 2; ++mf)
#pragma unroll
        for (int nf = 0; nf < 4; ++nf)
#pragma unroll
            for (int i = 0; i < 4; ++i) acc[mf][nf][i] = 0.f;

    const int S = K >> 5;
    for (int s = 0; s < S; ++s) {
#pragma unroll
        for (int u = 0; u < 4; ++u)
            *reinterpret_cast<float4*>(&As[arow * PAP + apart + u * 4]) = ra[u];
#pragma unroll
        for (int u = 0; u < 2; ++u)
            *reinterpret_cast<float4*>(&Bs[brow * PAP + bpart + u * 4]) = rb[u];
        __syncthreads();

        if (s + 1 < S) {
            const size_t off = (size_t)(s + 1) * 32;
#pragma unroll
            for (int u = 0; u < 4; ++u)
                ra[u] = *reinterpret_cast<const float4*>(apg + off + u * 4);
#pragma unroll
            for (int u = 0; u < 2; ++u)
                rb[u] = *reinterpret_cast<const float4*>(bpg + off + u * 4);
        }

#pragma unroll
        for (int kf = 0; kf < 4; ++kf) {
            uint32_t ah[2][4], al[2][4];
#pragma unroll
            for (int mf = 0; mf < 2; ++mf) {
                const int o = (wm * 32 + mf * 16 + g) * PAP + kf * 8 + tg;
                split_tf32(As[o],               ah[mf][0], al[mf][0]);
                split_tf32(As[o + 8 * PAP],     ah[mf][1], al[mf][1]);
                split_tf32(As[o + 4],           ah[mf][2], al[mf][2]);
                split_tf32(As[o + 8 * PAP + 4], ah[mf][3], al[mf][3]);
            }
            uint32_t bh[4][2], bl[4][2];
#pragma unroll
            for (int nf = 0; nf < 4; ++nf) {
                const int o = (wn * 32 + nf * 8 + g) * PAP + kf * 8 + tg;
                split_tf32(Bs[o],     bh[nf][0], bl[nf][0]);
                split_tf32(Bs[o + 4], bh[nf][1], bl[nf][1]);
            }
#pragma unroll
            for (int mf = 0; mf < 2; ++mf) {
#pragma unroll
                for (int nf = 0; nf < 4; ++nf) {
                    mma_tf32(acc[mf][nf][0], acc[mf][nf][1],
                             acc[mf][nf][2], acc[mf][nf][3],
                             ah[mf][0], ah[mf][1], ah[mf][2], ah[mf][3],
                             bh[nf][0], bh[nf][1]);
                    mma_tf32(acc[mf][nf][0], acc[mf][nf][1],
                             acc[mf][nf][2], acc[mf][nf][3],
                             al[mf][0], al[mf][1], al[mf][2], al[mf][3],
                             bh[nf][0], bh[nf][1]);
                    mma_tf32(acc[mf][nf][0], acc[mf][nf][1],
                             acc[mf][nf][2], acc[mf][nf][3],
                             ah[mf][0], ah[mf][1], ah[mf][2], ah[mf][3],
                             bl[nf][0], bl[nf][1]);
                }
            }
        }
        __syncthreads();
    }

#pragma unroll
    for (int nf = 0; nf < 4; ++nf) {
        const int n = n0 + wn * 32 + nf * 8 + 2 * tg;
        const float b0 = bias1[n] + bias2[n];
        const float b1 = bias1[n + 1] + bias2[n + 1];
#pragma unroll
        for (int mf = 0; mf < 2; ++mf) {
            const int m = m0 + wm * 32 + mf * 16 + g;
            *reinterpret_cast<float2*>(&out[(size_t)m * Hsz + n]) =
                make_float2(acc[mf][nf][0] + b0, acc[mf][nf][1] + b1);
            *reinterpret_cast<float2*>(&out[(size_t)(m + 8) * Hsz + n]) =
                make_float2(acc[mf][nf][2] + b0, acc[mf][nf][3] + b1);
        }
    }
}

// ---------------------------------------------------------------------------
// Flag post (block-wide: all this CTA's h_t writes are published).
// ---------------------------------------------------------------------------
__device__ __forceinline__ void flag_post(int cta, unsigned val)
{
    __syncthreads();                 // also protects red/As reuse across steps
    if (threadIdx.x == 0) {
        __threadfence();             // release
        *(volatile unsigned*)&g_flag[cta * 32] = val;
    }
}

// ---------------------------------------------------------------------------
// Tensor-core recurrence, 512 threads / 16 warps per CTA.
// CTA tile: 32 batch rows x 32 hidden cols. Warp w owns k-slice
// [32w, 32w+32), produced by exactly ONE CTA: (tile_m, w) -> single-flag
// broadcast poll per warp. Each warp: poll -> stage 4KB raw fp32 ->
// syncwarp -> 96 MMAs (tf32 hi/lo split at frag load) -> own red region.
// 4 warps/SMSP hide the LDS->split->MMA chains that capped R15 at 2/SMSP.
// ---------------------------------------------------------------------------
#define REC_AP 516
#define RED_PITCH 34
#define RED_WSTRIDE (32 * RED_PITCH)
#define REC_SMEM_FLOATS (32 * REC_AP + 16 * RED_WSTRIDE)
#define REC_SMEM_BYTES (REC_SMEM_FLOATS * 4)    // 135680 B

__global__ void __launch_bounds__(512) rnn_rec_mma(
    float* __restrict__ buf, const float* __restrict__ Whh)
{
    extern __shared__ float sm[];
    float* As  = sm;                  // [32][REC_AP] raw fp32 h_{t-1}
    float* red = sm + 32 * REC_AP;    // [16][RED_WSTRIDE]

    const int tid  = threadIdx.x;
    const int cta  = blockIdx.x;
    const int wid  = tid >> 5;        // warp 0..15 -> 32-wide k-slice
    const int lane = tid & 31;
    const int g    = lane >> 2;
    const int tg   = lane & 3;

    const int tile_m = cta >> 4;
    const int tile_n = cta & 15;
    const int b0 = tile_m * 32;
    const int n0 = tile_n * 32;

    // W_hh fragments (hi/lo) in registers; warp wid owns k in [32wid, 32wid+32).
    uint32_t Bhi[4][4][2], Blo[4][4][2];
#pragma unroll
    for (int nf = 0; nf < 4; ++nf) {
#pragma unroll
        for (int kf = 0; kf < 4; ++kf) {
            const float* wp = Whh + (size_t)(n0 + nf * 8 + g) * Hsz
                            + wid * 32 + kf * 8 + tg;
            float w0 = wp[0];
            float w1 = wp[4];
            uint32_t h0 = f2tf32(w0);
            uint32_t h1 = f2tf32(w1);
            Bhi[nf][kf][0] = h0;
            Bhi[nf][kf][1] = h1;
            Blo[nf][kf][0] = f2tf32(w0 - __uint_as_float(h0));
            Blo[nf][kf][1] = f2tf32(w1 - __uint_as_float(h1));
        }
    }

    // t = 0: h_0 = relu(proj_0)
    for (int i = tid; i < 32 * 32; i += 512) {
        int rr = i >> 5;
        int c  = i & 31;
        float* p = buf + ((size_t)(b0 + rr) * Tsz + 0) * Hsz + n0 + c;
        *p = fmaxf(*p, 0.f);
    }
    flag_post(cta, 1u);

    // This warp's single producer flag (broadcast poll).
    const int prod = (tile_m * 16 + wid) * 32;
    const int abase = g * REC_AP + wid * 32 + tg;

    for (int t = 1; t < Tsz; ++t) {
        // -- Warp-local wait on the one producer of this k-slice. --
        while (*(volatile unsigned*)&g_flag[prod] < (unsigned)t) { }
        __threadfence();             // acquire
        __syncwarp();

        // -- Stage this warp's own 4KB k-slice (raw fp32). --
        {
            const float* src = buf + ((size_t)b0 * Tsz + (t - 1)) * Hsz
                             + wid * 32;
            float* dst = As + wid * 32;
#pragma unroll
            for (int i = 0; i < 8; ++i) {
                int idx = i * 32 + lane;          // 0..255
                int rr = idx >> 3;                // 0..31
                int c  = (idx & 7) * 4;           // 0..28
                float4 v = *reinterpret_cast<const float4*>(
                    src + (size_t)rr * (Tsz * Hsz) + c);
                *reinterpret_cast<float4*>(dst + rr * REC_AP + c) = v;
            }
        }
        __syncwarp();

        // -- MMA over this warp's k-slice; split to hi/lo at frag load. --
        float acc[2][4][4];
#pragma unroll
        for (int mf = 0; mf < 2; ++mf)
#pragma unroll
            for (int nf = 0; nf < 4; ++nf)
#pragma unroll
                for (int i = 0; i < 4; ++i) acc[mf][nf][i] = 0.f;

#pragma unroll
        for (int kf = 0; kf < 4; ++kf) {
#pragma unroll
            for (int mf = 0; mf < 2; ++mf) {
                const int off = abase + kf * 8 + mf * (16 * REC_AP);
                uint32_t ah0, ah1, ah2, ah3, al0, al1, al2, al3;
                split_tf32(As[off],                  ah0, al0);
                split_tf32(As[off + 8 * REC_AP],     ah1, al1);
                split_tf32(As[off + 4],              ah2, al2);
                split_tf32(As[off + 8 * REC_AP + 4], ah3, al3);
#pragma unroll
                for (int nf = 0; nf < 4; ++nf) {
                    mma_tf32(acc[mf][nf][0], acc[mf][nf][1],
                             acc[mf][nf][2], acc[mf][nf][3],
                             ah0, ah1, ah2, ah3,
                             Bhi[nf][kf][0], Bhi[nf][kf][1]);
                    mma_tf32(acc[mf][nf][0], acc[mf][nf][1],
                             acc[mf][nf][2], acc[mf][nf][3],
                             al0, al1, al2, al3,
                             Bhi[nf][kf][0], Bhi[nf][kf][1]);
                    mma_tf32(acc[mf][nf][0], acc[mf][nf][1],
                             acc[mf][nf][2], acc[mf][nf][3],
                             ah0, ah1, ah2, ah3,
                             Blo[nf][kf][0], Blo[nf][kf][1]);
                }
            }
        }

        // -- Partial stores to this warp's own red region. --
        {
            float* rw = red + wid * RED_WSTRIDE;
#pragma unroll
            for (int mf = 0; mf < 2; ++mf) {
#pragma unroll
                for (int nf = 0; nf < 4; ++nf) {
                    int m = mf * 16 + g;
                    int n = nf * 8 + 2 * tg;
                    *reinterpret_cast<float2*>(&rw[m * RED_PITCH + n]) =
                        make_float2(acc[mf][nf][0], acc[mf][nf][1]);
                    *reinterpret_cast<float2*>(&rw[(m + 8) * RED_PITCH + n]) =
                        make_float2(acc[mf][nf][2], acc[mf][nf][3]);
                }
            }
        }
        __syncthreads();   // all 16 warps' partials visible

        // -- Reduce 16 warps' partials; h_t = relu(proj_t + sum), in place. --
        {
            int m  = tid >> 4;          // 0..31
            int nc = (tid & 15) * 2;    // 0..30
            float2 s = make_float2(0.f, 0.f);
#pragma unroll
            for (int w = 0; w < 16; ++w) {
                float2 v = *reinterpret_cast<const float2*>(
                    red + w * RED_WSTRIDE + m * RED_PITCH + nc);
                s.x += v.x; s.y += v.y;
            }
            float* p = buf + ((size_t)(b0 + m) * Tsz + t) * Hsz + n0 + nc;
            float2 q = *reinterpret_cast<float2*>(p);
            q.x = fmaxf(q.x + s.x, 0.f);
            q.y = fmaxf(q.y + s.y, 0.f);
            *reinterpret_cast<float2*>(p) = q;
        }

        if (t < Tsz - 1) flag_post(cta, (unsigned)(t + 1));
    }
}

// ---------------------------------------------------------------------------
// Final FC: out[b,c] = sum_i flat[b,i] * Wfc[c,i] + bfc[c]
// 64 CTAs; each handles 4 batch rows.
// ---------------------------------------------------------------------------
__global__ void __launch_bounds__(256) fc_kernel(
    const float* __restrict__ flat, const float* __restrict__ Wfc,
    const float* __restrict__ bfc, float* __restrict__ out)
{
    const int b = blockIdx.x;   // 0..63
    const float* xr[4];
#pragma unroll
    for (int rr = 0; rr < 4; ++rr)
        xr[rr] = flat + (size_t)(b + rr * 64) * (Tsz * Hsz);

    float acc[4][Csz];
#pragma unroll
    for (int rr = 0; rr < 4; ++rr)
#pragma unroll
        for (int c = 0; c < Csz; ++c) acc[rr][c] = 0.f;

    for (int i = threadIdx.x * 4; i < Tsz * Hsz; i += 256 * 4) {
        float4 x[4];
#pragma unroll
        for (int rr = 0; rr < 4; ++rr)
            x[rr] = *reinterpret_cast<const float4*>(xr[rr] + i);
#pragma unroll
        for (int c = 0; c < Csz; ++c) {
            float4 w = *reinterpret_cast<const float4*>(
                Wfc + (size_t)c * (Tsz * Hsz) + i);
#pragma unroll
            for (int rr = 0; rr < 4; ++rr)
                acc[rr][c] += x[rr].x * w.x + x[rr].y * w.y
                            + x[rr].z * w.z + x[rr].w * w.w;
        }
    }

#pragma unroll
    for (int rr = 0; rr < 4; ++rr)
#pragma unroll
        for (int c = 0; c < Csz; ++c)
#pragma unroll
            for (int off = 16; off > 0; off >>= 1)
                acc[rr][c] += __shfl_down_sync(0xffffffffu, acc[rr][c], off);

    __shared__ float part[4][Csz][8];
    const int warp = threadIdx.x >> 5;
    const int lane = threadIdx.x & 31;
    if (lane == 0) {
#pragma unroll
        for (int rr = 0; rr < 4; ++rr)
#pragma unroll
            for (int c = 0; c < Csz; ++c) part[rr][c][warp] = acc[rr][c];
    }
    __syncthreads();
    if (threadIdx.x < 4 * Csz) {
        int rr = threadIdx.x / Csz;
        int c  = threadIdx.x % Csz;
        float s = 0.f;
#pragma unroll
        for (int w = 0; w < 8; ++w) s += part[rr][c][w];
        out[(b + rr * 64) * Csz + c] = s + bfc[c];
    }
}

// ---------------------------------------------------------------------------
// kernel_launch: proj0 -> reset,rec0 -> proj1 -> reset,rec1 -> fc
// ---------------------------------------------------------------------------
extern "C" void kernel_launch(void* const* d_in, const int* in_sizes, int n_in,
                              void* d_out, int out_size)
{
    (void)in_sizes; (void)n_in; (void)out_size;
    const float* x     = (const float*)d_in[0];
    const float* W_ih0 = (const float*)d_in[1];
    const float* W_hh0 = (const float*)d_in[2];
    const float* b_ih0 = (const float*)d_in[3];
    const float* b_hh0 = (const float*)d_in[4];
    const float* W_ih1 = (const float*)d_in[5];
    const float* W_hh1 = (const float*)d_in[6];
    const float* b_ih1 = (const float*)d_in[7];
    const float* b_hh1 = (const float*)d_in[8];
    const float* W_fc  = (const float*)d_in[9];
    const float* b_fc  = (const float*)d_in[10];
    float* out = (float*)d_out;

    float* buf0 = nullptr;
    float* buf1 = nullptr;
    cudaGetSymbolAddress((void**)&buf0, g_buf0);
    cudaGetSymbolAddress((void**)&buf1, g_buf1);

    cudaFuncSetAttribute(rnn_rec_mma,
                         cudaFuncAttributeMaxDynamicSharedMemorySize,
                         REC_SMEM_BYTES);
    cudaFuncSetAttribute(proj_mma,
                         cudaFuncAttributeMaxDynamicSharedMemorySize,
                         PJ_SMEM_BYTES);

    dim3 pgrid(Hsz / 64, (Bsz * Tsz) / 128);   // (8, 256)

    // Layer 0
    proj_mma<<<pgrid, 256, PJ_SMEM_BYTES>>>(x, W_ih0, b_ih0, b_hh0, buf0, Fsz);
    reset_flags<<<1, 128>>>();
    rnn_rec_mma<<<REC_NBLK, 512, REC_SMEM_BYTES>>>(buf0, W_hh0);

    // Layer 1
    proj_mma<<<pgrid, 256, PJ_SMEM_BYTES>>>(buf0, W_ih1, b_ih1, b_hh1, buf1, Hsz);
    reset_flags<<<1, 128>>>();
    rnn_rec_mma<<<REC_NBLK, 512, REC_SMEM_BYTES>>>(buf1, W_hh1);

    // Classifier
    fc_kernel<<<64, 256>>>(buf1, W_fc, b_fc, out);
}

// round 17
// speedup vs baseline: 1.0309x; 1.0309x over previous
#include <cuda_runtime.h>
#include <cstdint>

#define Bsz 256
#define Tsz 128
#define Fsz 256
#define Hsz 512
#define Csz 10

// Scratch: proj/h buffers, written in place by the recurrence.
__device__ float g_buf0[Bsz * Tsz * Hsz];   // 64 MB
__device__ float g_buf1[Bsz * Tsz * Hsz];   // 64 MB

// Distributed barrier: one padded flag per CTA (128B apart).
#define REC_NBLK 128
__device__ unsigned g_flag[REC_NBLK * 32];

__global__ void reset_flags()
{
    if (threadIdx.x < REC_NBLK) g_flag[threadIdx.x * 32] = 0u;
}

// ---------------------------------------------------------------------------
// TF32 helpers (shared by recurrence and projection).
// ---------------------------------------------------------------------------
__device__ __forceinline__ uint32_t f2tf32(float x)
{
    uint32_t r;
    asm("cvt.rna.tf32.f32 %0, %1;" : "=r"(r) : "f"(x));
    return r;
}

__device__ __forceinline__ void mma_tf32(
    float& d0, float& d1, float& d2, float& d3,
    uint32_t a0, uint32_t a1, uint32_t a2, uint32_t a3,
    uint32_t b0, uint32_t b1)
{
    asm volatile(
        "mma.sync.aligned.m16n8k8.row.col.f32.tf32.tf32.f32 "
        "{%0,%1,%2,%3}, {%4,%5,%6,%7}, {%8,%9}, {%0,%1,%2,%3};\n"
        : "+f"(d0), "+f"(d1), "+f"(d2), "+f"(d3)
        : "r"(a0), "r"(a1), "r"(a2), "r"(a3), "r"(b0), "r"(b1));
}

// Split one fp32 value into tf32 hi + lo residual (as tf32-able f32).
__device__ __forceinline__ void split_tf32(float v, uint32_t& hi, uint32_t& lo)
{
    hi = f2tf32(v);
    lo = __float_as_uint(v - __uint_as_float(hi));
}

// ---------------------------------------------------------------------------
// Tensor-core projection GEMM with DOUBLE-BUFFERED smem.
// out[m,n] = sum_k A[m,k]*Wt[n,k] + b1[n]+b2[n]. 3xTF32 split.
// BM=128, BN=64, BK=32. 8 warps in 4m x 2n grid; warp tile 32x32.
// Iteration s: prefetch chunk s+1 (LDG) -> compute from buf[s%2] ->
// stage regs into buf[(s+1)%2] -> ONE syncthreads. Tensor pipe no longer
// idles during staging; one barrier per chunk instead of two.
// Smem pitch 36: bank = (4*row + k) mod 32 -> conflict-free.
// ---------------------------------------------------------------------------
#define PAP 36
#define PJ_BUF_FLOATS (128 * PAP + 64 * PAP)          // 6912 floats per stage
#define PJ_SMEM_BYTES (2 * PJ_BUF_FLOATS * 4)         // 55296 B

__global__ void __launch_bounds__(256, 2) proj_mma(
    const float* __restrict__ A, const float* __restrict__ Wt,
    const float* __restrict__ bias1, const float* __restrict__ bias2,
    float* __restrict__ out, int K)
{
    extern __shared__ float psm[];

    const int tid  = threadIdx.x;
    const int w    = tid >> 5;
    const int lane = tid & 31;
    const int wm   = w & 3;
    const int wn   = w >> 2;
    const int g    = lane >> 2;
    const int tg   = lane & 3;

    const int m0 = blockIdx.y * 128;
    const int n0 = blockIdx.x * 64;

    const int arow  = tid >> 1;
    const int apart = (tid & 1) * 16;
    const float* apg = A + (size_t)(m0 + arow) * K + apart;
    const int brow  = tid >> 2;
    const int bpart = (tid & 3) * 8;
    const float* bpg = Wt + (size_t)(n0 + brow) * K + bpart;

    float4 ra[4], rb[2];
#pragma unroll
    for (int u = 0; u < 4; ++u)
        ra[u] = *reinterpret_cast<const float4*>(apg + u * 4);
#pragma unroll
    for (int u = 0; u < 2; ++u)
        rb[u] = *reinterpret_cast<const float4*>(bpg + u * 4);

    float acc[2][4][4];
#pragma unroll
    for (int mf = 0; mf < 2; ++mf)
#pragma unroll
        for (int nf = 0; nf < 4; ++nf)
#pragma unroll
            for (int i = 0; i < 4; ++i) acc[mf][nf][i] = 0.f;

    // Prologue: stage chunk 0 into buffer 0.
    {
        float* As0 = psm;
        float* Bs0 = psm + 128 * PAP;
#pragma unroll
        for (int u = 0; u < 4; ++u)
            *reinterpret_cast<float4*>(&As0[arow * PAP + apart + u * 4]) = ra[u];
#pragma unroll
        for (int u = 0; u < 2; ++u)
            *reinterpret_cast<float4*>(&Bs0[brow * PAP + bpart + u * 4]) = rb[u];
    }
    __syncthreads();

    const int S = K >> 5;
    for (int s = 0; s < S; ++s) {
        const int cur = s & 1;
        const float* As = psm + cur * PJ_BUF_FLOATS;
        const float* Bs = As + 128 * PAP;

        // Prefetch chunk s+1 from global (latency hidden behind MMAs).
        const bool more = (s + 1 < S);
        if (more) {
            const size_t off = (size_t)(s + 1) * 32;
#pragma unroll
            for (int u = 0; u < 4; ++u)
                ra[u] = *reinterpret_cast<const float4*>(apg + off + u * 4);
#pragma unroll
            for (int u = 0; u < 2; ++u)
                rb[u] = *reinterpret_cast<const float4*>(bpg + off + u * 4);
        }

        // Compute chunk s from buf[cur].
#pragma unroll
        for (int kf = 0; kf < 4; ++kf) {
            uint32_t ah[2][4], al[2][4];
#pragma unroll
            for (int mf = 0; mf < 2; ++mf) {
                const int o = (wm * 32 + mf * 16 + g) * PAP + kf * 8 + tg;
                split_tf32(As[o],               ah[mf][0], al[mf][0]);
                split_tf32(As[o + 8 * PAP],     ah[mf][1], al[mf][1]);
                split_tf32(As[o + 4],           ah[mf][2], al[mf][2]);
                split_tf32(As[o + 8 * PAP + 4], ah[mf][3], al[mf][3]);
            }
            uint32_t bh[4][2], bl[4][2];
#pragma unroll
            for (int nf = 0; nf < 4; ++nf) {
                const int o = (wn * 32 + nf * 8 + g) * PAP + kf * 8 + tg;
                split_tf32(Bs[o],     bh[nf][0], bl[nf][0]);
                split_tf32(Bs[o + 4], bh[nf][1], bl[nf][1]);
            }
#pragma unroll
            for (int mf = 0; mf < 2; ++mf) {
#pragma unroll
                for (int nf = 0; nf < 4; ++nf) {
                    mma_tf32(acc[mf][nf][0], acc[mf][nf][1],
                             acc[mf][nf][2], acc[mf][nf][3],
                             ah[mf][0], ah[mf][1], ah[mf][2], ah[mf][3],
                             bh[nf][0], bh[nf][1]);
                    mma_tf32(acc[mf][nf][0], acc[mf][nf][1],
                             acc[mf][nf][2], acc[mf][nf][3],
                             al[mf][0], al[mf][1], al[mf][2], al[mf][3],
                             bh[nf][0], bh[nf][1]);
                    mma_tf32(acc[mf][nf][0], acc[mf][nf][1],
                             acc[mf][nf][2], acc[mf][nf][3],
                             ah[mf][0], ah[mf][1], ah[mf][2], ah[mf][3],
                             bl[nf][0], bl[nf][1]);
                }
            }
        }

        // Stage chunk s+1 into the other buffer (readers of buf[cur^1]
        // all passed the previous sync; writers vs readers of buf[cur]
        // are separated by the sync below).
        if (more) {
            float* Asn = psm + (cur ^ 1) * PJ_BUF_FLOATS;
            float* Bsn = Asn + 128 * PAP;
#pragma unroll
            for (int u = 0; u < 4; ++u)
                *reinterpret_cast<float4*>(&Asn[arow * PAP + apart + u * 4]) = ra[u];
#pragma unroll
            for (int u = 0; u < 2; ++u)
                *reinterpret_cast<float4*>(&Bsn[brow * PAP + bpart + u * 4]) = rb[u];
            __syncthreads();
        }
    }

    // Epilogue: add biases, write fp32.
#pragma unroll
    for (int nf = 0; nf < 4; ++nf) {
        const int n = n0 + wn * 32 + nf * 8 + 2 * tg;
        const float b0 = bias1[n] + bias2[n];
        const float b1 = bias1[n + 1] + bias2[n + 1];
#pragma unroll
        for (int mf = 0; mf < 2; ++mf) {
            const int m = m0 + wm * 32 + mf * 16 + g;
            *reinterpret_cast<float2*>(&out[(size_t)m * Hsz + n]) =
                make_float2(acc[mf][nf][0] + b0, acc[mf][nf][1] + b1);
            *reinterpret_cast<float2*>(&out[(size_t)(m + 8) * Hsz + n]) =
                make_float2(acc[mf][nf][2] + b0, acc[mf][nf][3] + b1);
        }
    }
}

// ---------------------------------------------------------------------------
// Flag post (block-wide: all this CTA's h_t writes are published).
// ---------------------------------------------------------------------------
__device__ __forceinline__ void flag_post(int cta, unsigned val)
{
    __syncthreads();                 // also protects red/As reuse across steps
    if (threadIdx.x == 0) {
        __threadfence();             // release
        *(volatile unsigned*)&g_flag[cta * 32] = val;
    }
}

// ---------------------------------------------------------------------------
// Tensor-core recurrence — EXACT R15 configuration (best measured).
// 128 CTAs x 256 threads. CTA tile: 32 batch rows x 32 hidden cols.
// Warp w owns k-slice [64w, 64w+64), produced by the 2 CTAs
// (tile_m, 2w) and (tile_m, 2w+1). Warp-level dataflow sync.
// ---------------------------------------------------------------------------
#define REC_AP 516
#define RED_PITCH 34
#define RED_WSTRIDE (32 * RED_PITCH)
#define REC_SMEM_FLOATS (32 * REC_AP + 8 * RED_WSTRIDE)
#define REC_SMEM_BYTES (REC_SMEM_FLOATS * 4)    // 100864 B

__global__ void __launch_bounds__(256) rnn_rec_mma(
    float* __restrict__ buf, const float* __restrict__ Whh)
{
    extern __shared__ float sm[];
    float* As  = sm;                  // [32][REC_AP] raw fp32 h_{t-1}
    float* red = sm + 32 * REC_AP;    // [8][RED_WSTRIDE]

    const int tid  = threadIdx.x;
    const int cta  = blockIdx.x;
    const int wid  = tid >> 5;
    const int lane = tid & 31;
    const int g    = lane >> 2;
    const int tg   = lane & 3;

    const int tile_m = cta >> 4;
    const int tile_n = cta & 15;
    const int b0 = tile_m * 32;
    const int n0 = tile_n * 32;

    uint32_t Bhi[4][8][2], Blo[4][8][2];
#pragma unroll
    for (int nf = 0; nf < 4; ++nf) {
#pragma unroll
        for (int kf = 0; kf < 8; ++kf) {
            const float* wp = Whh + (size_t)(n0 + nf * 8 + g) * Hsz
                            + wid * 64 + kf * 8 + tg;
            float w0 = wp[0];
            float w1 = wp[4];
            uint32_t h0 = f2tf32(w0);
            uint32_t h1 = f2tf32(w1);
            Bhi[nf][kf][0] = h0;
            Bhi[nf][kf][1] = h1;
            Blo[nf][kf][0] = f2tf32(w0 - __uint_as_float(h0));
            Blo[nf][kf][1] = f2tf32(w1 - __uint_as_float(h1));
        }
    }

    // t = 0: h_0 = relu(proj_0)
    for (int i = tid; i < 32 * 32; i += 256) {
        int rr = i >> 5;
        int c  = i & 31;
        float* p = buf + ((size_t)(b0 + rr) * Tsz + 0) * Hsz + n0 + c;
        *p = fmaxf(*p, 0.f);
    }
    flag_post(cta, 1u);

    const int prod = (tile_m * 16 + wid * 2 + (lane & 1)) * 32;
    const int abase = g * REC_AP + wid * 64 + tg;

    for (int t = 1; t < Tsz; ++t) {
        // -- Warp-local wait: only this warp's 2 producers must be done. --
        while (*(volatile unsigned*)&g_flag[prod] < (unsigned)t) { }
        __threadfence();             // per-lane acquire
        __syncwarp();

        // -- Stage this warp's own 8KB k-slice (raw fp32). --
        {
            const float* src = buf + ((size_t)b0 * Tsz + (t - 1)) * Hsz
                             + wid * 64;
            float* dst = As + wid * 64;
#pragma unroll
            for (int i = 0; i < 16; ++i) {
                int idx = i * 32 + lane;
                int rr = idx >> 4;
                int c  = (idx & 15) * 4;
                float4 v = *reinterpret_cast<const float4*>(
                    src + (size_t)rr * (Tsz * Hsz) + c);
                *reinterpret_cast<float4*>(dst + rr * REC_AP + c) = v;
            }
        }
        __syncwarp();

        // -- MMA over this warp's k-slice; split to hi/lo at frag load. --
        float acc[2][4][4];
#pragma unroll
        for (int mf = 0; mf < 2; ++mf)
#pragma unroll
            for (int nf = 0; nf < 4; ++nf)
#pragma unroll
                for (int i = 0; i < 4; ++i) acc[mf][nf][i] = 0.f;

#pragma unroll
        for (int kf = 0; kf < 8; ++kf) {
#pragma unroll
            for (int mf = 0; mf < 2; ++mf) {
                const int off = abase + kf * 8 + mf * (16 * REC_AP);
                uint32_t ah0, ah1, ah2, ah3, al0, al1, al2, al3;
                split_tf32(As[off],                  ah0, al0);
                split_tf32(As[off + 8 * REC_AP],     ah1, al1);
                split_tf32(As[off + 4],              ah2, al2);
                split_tf32(As[off + 8 * REC_AP + 4], ah3, al3);
#pragma unroll
                for (int nf = 0; nf < 4; ++nf) {
                    mma_tf32(acc[mf][nf][0], acc[mf][nf][1],
                             acc[mf][nf][2], acc[mf][nf][3],
                             ah0, ah1, ah2, ah3,
                             Bhi[nf][kf][0], Bhi[nf][kf][1]);
                    mma_tf32(acc[mf][nf][0], acc[mf][nf][1],
                             acc[mf][nf][2], acc[mf][nf][3],
                             al0, al1, al2, al3,
                             Bhi[nf][kf][0], Bhi[nf][kf][1]);
                    mma_tf32(acc[mf][nf][0], acc[mf][nf][1],
                             acc[mf][nf][2], acc[mf][nf][3],
                             ah0, ah1, ah2, ah3,
                             Blo[nf][kf][0], Blo[nf][kf][1]);
                }
            }
        }

        // -- Partial stores to this warp's own red region. --
        {
            float* rw = red + wid * RED_WSTRIDE;
#pragma unroll
            for (int mf = 0; mf < 2; ++mf) {
#pragma unroll
                for (int nf = 0; nf < 4; ++nf) {
                    int m = mf * 16 + g;
                    int n = nf * 8 + 2 * tg;
                    *reinterpret_cast<float2*>(&rw[m * RED_PITCH + n]) =
                        make_float2(acc[mf][nf][0], acc[mf][nf][1]);
                    *reinterpret_cast<float2*>(&rw[(m + 8) * RED_PITCH + n]) =
                        make_float2(acc[mf][nf][2], acc[mf][nf][3]);
                }
            }
        }
        __syncthreads();   // all warps' partials visible

        // -- Reduce 8 warps' partials; h_t = relu(proj_t + sum), in place. --
        {
            int m  = tid >> 3;
            int nc = (tid & 7) * 4;
            float2 s0 = make_float2(0.f, 0.f);
            float2 s1 = make_float2(0.f, 0.f);
#pragma unroll
            for (int w = 0; w < 8; ++w) {
                const float* rw = red + w * RED_WSTRIDE + m * RED_PITCH + nc;
                float2 v0 = *reinterpret_cast<const float2*>(rw);
                float2 v1 = *reinterpret_cast<const float2*>(rw + 2);
                s0.x += v0.x; s0.y += v0.y;
                s1.x += v1.x; s1.y += v1.y;
            }
            float* p = buf + ((size_t)(b0 + m) * Tsz + t) * Hsz + n0 + nc;
            float4 q = *reinterpret_cast<float4*>(p);
            q.x = fmaxf(q.x + s0.x, 0.f);
            q.y = fmaxf(q.y + s0.y, 0.f);
            q.z = fmaxf(q.z + s1.x, 0.f);
            q.w = fmaxf(q.w + s1.y, 0.f);
            *reinterpret_cast<float4*>(p) = q;
        }

        if (t < Tsz - 1) flag_post(cta, (unsigned)(t + 1));
        else __syncthreads();
    }
}

// ---------------------------------------------------------------------------
// Final FC: out[b,c] = sum_i flat[b,i] * Wfc[c,i] + bfc[c]
// 64 CTAs; each handles 4 batch rows.
// ---------------------------------------------------------------------------
__global__ void __launch_bounds__(256) fc_kernel(
    const float* __restrict__ flat, const float* __restrict__ Wfc,
    const float* __restrict__ bfc, float* __restrict__ out)
{
    const int b = blockIdx.x;   // 0..63
    const float* xr[4];
#pragma unroll
    for (int rr = 0; rr < 4; ++rr)
        xr[rr] = flat + (size_t)(b + rr * 64) * (Tsz * Hsz);

    float acc[4][Csz];
#pragma unroll
    for (int rr = 0; rr < 4; ++rr)
#pragma unroll
        for (int c = 0; c < Csz; ++c) acc[rr][c] = 0.f;

    for (int i = threadIdx.x * 4; i < Tsz * Hsz; i += 256 * 4) {
        float4 x[4];
#pragma unroll
        for (int rr = 0; rr < 4; ++rr)
            x[rr] = *reinterpret_cast<const float4*>(xr[rr] + i);
#pragma unroll
        for (int c = 0; c < Csz; ++c) {
            float4 w = *reinterpret_cast<const float4*>(
                Wfc + (size_t)c * (Tsz * Hsz) + i);
#pragma unroll
            for (int rr = 0; rr < 4; ++rr)
                acc[rr][c] += x[rr].x * w.x + x[rr].y * w.y
                            + x[rr].z * w.z + x[rr].w * w.w;
        }
    }

#pragma unroll
    for (int rr = 0; rr < 4; ++rr)
#pragma unroll
        for (int c = 0; c < Csz; ++c)
#pragma unroll
            for (int off = 16; off > 0; off >>= 1)
                acc[rr][c] += __shfl_down_sync(0xffffffffu, acc[rr][c], off);

    __shared__ float part[4][Csz][8];
    const int warp = threadIdx.x >> 5;
    const int lane = threadIdx.x & 31;
    if (lane == 0) {
#pragma unroll
        for (int rr = 0; rr < 4; ++rr)
#pragma unroll
            for (int c = 0; c < Csz; ++c) part[rr][c][warp] = acc[rr][c];
    }
    __syncthreads();
    if (threadIdx.x < 4 * Csz) {
        int rr = threadIdx.x / Csz;
        int c  = threadIdx.x % Csz;
        float s = 0.f;
#pragma unroll
        for (int w = 0; w < 8; ++w) s += part[rr][c][w];
        out[(b + rr * 64) * Csz + c] = s + bfc[c];
    }
}

// ---------------------------------------------------------------------------
// kernel_launch: proj0 -> reset,rec0 -> proj1 -> reset,rec1 -> fc
// ---------------------------------------------------------------------------
extern "C" void kernel_launch(void* const* d_in, const int* in_sizes, int n_in,
                              void* d_out, int out_size)
{
    (void)in_sizes; (void)n_in; (void)out_size;
    const float* x     = (const float*)d_in[0];
    const float* W_ih0 = (const float*)d_in[1];
    const float* W_hh0 = (const float*)d_in[2];
    const float* b_ih0 = (const float*)d_in[3];
    const float* b_hh0 = (const float*)d_in[4];
    const float* W_ih1 = (const float*)d_in[5];
    const float* W_hh1 = (const float*)d_in[6];
    const float* b_ih1 = (const float*)d_in[7];
    const float* b_hh1 = (const float*)d_in[8];
    const float* W_fc  = (const float*)d_in[9];
    const float* b_fc  = (const float*)d_in[10];
    float* out = (float*)d_out;

    float* buf0 = nullptr;
    float* buf1 = nullptr;
    cudaGetSymbolAddress((void**)&buf0, g_buf0);
    cudaGetSymbolAddress((void**)&buf1, g_buf1);

    cudaFuncSetAttribute(rnn_rec_mma,
                         cudaFuncAttributeMaxDynamicSharedMemorySize,
                         REC_SMEM_BYTES);
    cudaFuncSetAttribute(proj_mma,
                         cudaFuncAttributeMaxDynamicSharedMemorySize,
                         PJ_SMEM_BYTES);

    dim3 pgrid(Hsz / 64, (Bsz * Tsz) / 128);   // (8, 256)

    // Layer 0
    proj_mma<<<pgrid, 256, PJ_SMEM_BYTES>>>(x, W_ih0, b_ih0, b_hh0, buf0, Fsz);
    reset_flags<<<1, 128>>>();
    rnn_rec_mma<<<REC_NBLK, 256, REC_SMEM_BYTES>>>(buf0, W_hh0);

    // Layer 1
    proj_mma<<<pgrid, 256, PJ_SMEM_BYTES>>>(buf0, W_ih1, b_ih1, b_hh1, buf1, Hsz);
    reset_flags<<<1, 128>>>();
    rnn_rec_mma<<<REC_NBLK, 256, REC_SMEM_BYTES>>>(buf1, W_hh1);

    // Classifier
    fc_kernel<<<64, 256>>>(buf1, W_fc, b_fc, out);
}